// round 5
// baseline (speedup 1.0000x reference)
#include <cuda_runtime.h>
#include <cstdint>

#define NCLS   10
#define BLOCK  256
#define NGRID  (152 * 5)     // 5 blocks/SM @ <=51 regs -> exactly one wave
#define NWARPS (BLOCK / 32)

typedef unsigned long long ull;

__device__ float2       g_part[NGRID][NCLS];
__device__ unsigned int g_ticket = 0;

// One element -> 10 register accumulators; single fused asm block:
// pack {sq,1} once, then 10x (setp.eq; @p add.rn.f32x2).
__device__ __forceinline__ void acc_el(float o, float t, int m, ull* a) {
    float e  = o - t;
    float sq = e * e;
    int  key = (m == 1) ? (int)t : NCLS;   // dummy key 10 matches no class
    asm volatile(
        "{\n\t"
        ".reg .pred p;\n\t"
        ".reg .b64  inc;\n\t"
        "mov.b64 inc, {%10, %11};\n\t"
        "setp.eq.s32 p, %12, 0;\n\t @p add.rn.f32x2 %0, %0, inc;\n\t"
        "setp.eq.s32 p, %12, 1;\n\t @p add.rn.f32x2 %1, %1, inc;\n\t"
        "setp.eq.s32 p, %12, 2;\n\t @p add.rn.f32x2 %2, %2, inc;\n\t"
        "setp.eq.s32 p, %12, 3;\n\t @p add.rn.f32x2 %3, %3, inc;\n\t"
        "setp.eq.s32 p, %12, 4;\n\t @p add.rn.f32x2 %4, %4, inc;\n\t"
        "setp.eq.s32 p, %12, 5;\n\t @p add.rn.f32x2 %5, %5, inc;\n\t"
        "setp.eq.s32 p, %12, 6;\n\t @p add.rn.f32x2 %6, %6, inc;\n\t"
        "setp.eq.s32 p, %12, 7;\n\t @p add.rn.f32x2 %7, %7, inc;\n\t"
        "setp.eq.s32 p, %12, 8;\n\t @p add.rn.f32x2 %8, %8, inc;\n\t"
        "setp.eq.s32 p, %12, 9;\n\t @p add.rn.f32x2 %9, %9, inc;\n\t"
        "}"
        : "+l"(a[0]), "+l"(a[1]), "+l"(a[2]), "+l"(a[3]), "+l"(a[4]),
          "+l"(a[5]), "+l"(a[6]), "+l"(a[7]), "+l"(a[8]), "+l"(a[9])
        : "f"(sq), "f"(1.0f), "r"(key));
}

__global__ __launch_bounds__(BLOCK, 5) void loss_k(
    const float* __restrict__ outs,
    const float* __restrict__ tgts,
    const int*   __restrict__ mask,
    int n, float* __restrict__ out, int out_size)
{
    __shared__ float2 s_warp[NWARPS][NCLS];
    __shared__ float  le[NCLS];
    __shared__ unsigned int s_ticket;
    const int tid  = threadIdx.x;
    const int lane = tid & 31;
    const int wid  = tid >> 5;

    ull acc[NCLS];
    #pragma unroll
    for (int c = 0; c < NCLS; c++) acc[c] = 0ull;   // {0.0f, 0.0f}

    const int n4 = n >> 2;
    const float4* __restrict__ o4 = reinterpret_cast<const float4*>(outs);
    const float4* __restrict__ t4 = reinterpret_cast<const float4*>(tgts);
    const int4*   __restrict__ m4 = reinterpret_cast<const int4*>(mask);

    const int stride = NGRID * BLOCK;
    for (int i = blockIdx.x * BLOCK + tid; i < n4; i += stride) {
        float4 ov = __ldcs(o4 + i);     // streaming: touched once
        float4 tv = __ldcs(t4 + i);
        int4   mv = __ldcs(m4 + i);
        acc_el(ov.x, tv.x, mv.x, acc);
        acc_el(ov.y, tv.y, mv.y, acc);
        acc_el(ov.z, tv.z, mv.z, acc);
        acc_el(ov.w, tv.w, mv.w, acc);
    }
    if (blockIdx.x == 0) {               // scalar tail (n % 4)
        int j = (n4 << 2) + tid;
        if (j < n) acc_el(outs[j], tgts[j], mask[j], acc);
    }

    // ---- warp shuffle reduction (float2 packed in ull) ----
    #pragma unroll
    for (int off = 16; off > 0; off >>= 1) {
        #pragma unroll
        for (int c = 0; c < NCLS; c++) {
            ull other = __shfl_down_sync(0xffffffffu, acc[c], off);
            ull r;
            asm("add.rn.f32x2 %0, %1, %2;" : "=l"(r) : "l"(acc[c]), "l"(other));
            acc[c] = r;
        }
    }
    if (lane == 0) {
        #pragma unroll
        for (int c = 0; c < NCLS; c++) {
            float2 v;
            asm("mov.b64 {%0, %1}, %2;" : "=f"(v.x), "=f"(v.y) : "l"(acc[c]));
            s_warp[wid][c] = v;
        }
    }
    __syncthreads();

    // ---- per-block partial: threads 0..9 combine the warp rows ----
    if (tid < NCLS) {
        float2 p = make_float2(0.0f, 0.0f);
        #pragma unroll
        for (int w = 0; w < NWARPS; w++) {
            float2 v = s_warp[w][tid];
            p.x += v.x; p.y += v.y;
        }
        g_part[blockIdx.x][tid] = p;
    }
    __threadfence();
    __syncthreads();
    if (tid == 0) s_ticket = atomicAdd(&g_ticket, 1u);
    __syncthreads();
    if (s_ticket != (unsigned)(gridDim.x - 1)) return;

    // ---- last block: reduce partials, finalize, write output ----
    __threadfence();

    float2 racc[NCLS];
    #pragma unroll
    for (int c = 0; c < NCLS; c++) racc[c] = make_float2(0.0f, 0.0f);
    for (int j = tid; j < NGRID; j += BLOCK) {
        #pragma unroll
        for (int c = 0; c < NCLS; c++) {
            float2 p = g_part[j][c];
            racc[c].x += p.x;
            racc[c].y += p.y;
        }
    }
    #pragma unroll
    for (int off = 16; off > 0; off >>= 1) {
        #pragma unroll
        for (int c = 0; c < NCLS; c++) {
            racc[c].x += __shfl_down_sync(0xffffffffu, racc[c].x, off);
            racc[c].y += __shfl_down_sync(0xffffffffu, racc[c].y, off);
        }
    }
    if (lane == 0) {
        #pragma unroll
        for (int c = 0; c < NCLS; c++) s_warp[wid][c] = racc[c];
    }
    __syncthreads();

    if (tid < NCLS) {
        float2 tot = make_float2(0.0f, 0.0f);
        #pragma unroll
        for (int w = 0; w < NWARPS; w++) {
            float2 v = s_warp[w][tid];
            tot.x += v.x; tot.y += v.y;
        }
        s_warp[0][tid] = tot;
        le[tid] = (tot.y > 0.0f) ? (tot.x / fmaxf(tot.y, 1.0f)) : 0.0f;
    }
    __syncthreads();

    if (tid == 0) {
        float loss = 0.0f;
        #pragma unroll
        for (int c = 0; c < NCLS; c++) loss += 0.1f * le[c];
        out[0] = loss;
        g_ticket = 0;    // reset for graph replay determinism
    } else if (tid >= 1 && tid <= NCLS) {
        out[tid] = le[tid - 1];                  // loss_each
    } else if (tid >= NCLS + 1 && tid <= 2 * NCLS) {
        out[tid] = s_warp[0][tid - NCLS - 1].y;  // class_n
    } else if (tid < out_size) {
        out[tid] = 0.0f;
    }
}

extern "C" void kernel_launch(void* const* d_in, const int* in_sizes, int n_in,
                              void* d_out, int out_size) {
    const float* outs = (const float*)d_in[0];
    const float* tgts = (const float*)d_in[1];
    const int*   mask = (const int*)d_in[2];
    float* out = (float*)d_out;
    int n = in_sizes[0];

    loss_k<<<NGRID, BLOCK>>>(outs, tgts, mask, n, out, out_size);
}